// round 1
// baseline (speedup 1.0000x reference)
#include <cuda_runtime.h>
#include <cuda_bf16.h>
#include <cstdint>

// Greedy CTC decode:
//   emission: [T, V=128] fp32
//   out layout (fp32, 3*T elems): [ idx(0:T) | keep(T:2T) | path_score(2T:3T) ]
//
// Kernel 1: per-row argmax + max (one warp per row, coalesced float4 loads).
//           Writes idx as float into out[0:T], row max into out[2T:3T] (temp).
// Kernel 2: run-length dedup: keep[t] = (idx[t]!=idx[t-1]) && (idx[t]!=BLANK),
//           prev = -1 at t=0; path_score[t] = keep ? max : 0 (in place on 2T:3T).

#define V 128
#define BLANK 0
#define WARPS_PER_BLOCK 8
#define FULL_MASK 0xFFFFFFFFu

__global__ void __launch_bounds__(WARPS_PER_BLOCK * 32)
ctc_argmax_kernel(const float* __restrict__ em,
                  float* __restrict__ out_idx,
                  float* __restrict__ out_max,
                  int rows)
{
    const int warp_in_block = threadIdx.x >> 5;
    const int lane = threadIdx.x & 31;
    const int row = blockIdx.x * WARPS_PER_BLOCK + warp_in_block;
    if (row >= rows) return;

    // Coalesced: lane L loads columns [4L, 4L+4)
    const float4 v = reinterpret_cast<const float4*>(em + (size_t)row * V)[lane];

    // Local argmax over 4, first-occurrence tie-break (strict > keeps earliest)
    float best = v.x;
    int bi = lane * 4;
    if (v.y > best) { best = v.y; bi = lane * 4 + 1; }
    if (v.z > best) { best = v.z; bi = lane * 4 + 2; }
    if (v.w > best) { best = v.w; bi = lane * 4 + 3; }

    // Butterfly reduce: carry (max, idx); tie-break to lowest index
    #pragma unroll
    for (int off = 16; off > 0; off >>= 1) {
        float ov = __shfl_xor_sync(FULL_MASK, best, off);
        int   oi = __shfl_xor_sync(FULL_MASK, bi,   off);
        if (ov > best || (ov == best && oi < bi)) { best = ov; bi = oi; }
    }

    if (lane == 0) {
        out_idx[row] = (float)bi;
        out_max[row] = best;   // parked in path_score slot; masked by kernel 2
    }
}

__global__ void __launch_bounds__(256)
ctc_dedup_kernel(const float* __restrict__ idx_f,   // out[0:T]
                 float* __restrict__ keep_f,        // out[T:2T]
                 float* __restrict__ score_f,       // out[2T:3T], holds max in, score out
                 int rows)
{
    int t = blockIdx.x * blockDim.x + threadIdx.x;
    if (t >= rows) return;

    float cur  = idx_f[t];
    float prev = (t > 0) ? idx_f[t - 1] : -1.0f;
    bool keep = (cur != prev) && (cur != (float)BLANK);

    keep_f[t]  = keep ? 1.0f : 0.0f;
    score_f[t] = keep ? score_f[t] : 0.0f;
}

extern "C" void kernel_launch(void* const* d_in, const int* in_sizes, int n_in,
                              void* d_out, int out_size)
{
    const float* em = (const float*)d_in[0];
    float* out = (float*)d_out;

    const int rows = in_sizes[0] / V;       // T = 1048576
    float* out_idx   = out;                  // [0:T)
    float* out_keep  = out + rows;           // [T:2T)
    float* out_score = out + 2 * (size_t)rows; // [2T:3T)

    {
        dim3 block(WARPS_PER_BLOCK * 32);
        dim3 grid((rows + WARPS_PER_BLOCK - 1) / WARPS_PER_BLOCK);
        ctc_argmax_kernel<<<grid, block>>>(em, out_idx, out_score, rows);
    }
    {
        dim3 block(256);
        dim3 grid((rows + 255) / 256);
        ctc_dedup_kernel<<<grid, block>>>(out_idx, out_keep, out_score, rows);
    }
}

// round 2
// speedup vs baseline: 1.5168x; 1.5168x over previous
#include <cuda_runtime.h>
#include <cuda_bf16.h>
#include <cstdint>

// Greedy CTC decode:
//   emission: [T, V=128] fp32
//   out (fp32, 3*T): [ idx(0:T) | keep(T:2T) | path_score(2T:3T) ]
//
// Kernel 1: warp handles 8 consecutive rows. 8 independent float4 LDGs up
//           front (MLP=8), then per-row reduce via monotone-u32 REDUX max +
//           ballot (lowest lane = first-occurrence argmax) + 1 shfl.
// Kernel 2: vectorized run-length dedup + score masking.

#define V 128
#define BLANK 0
#define WARPS_PER_BLOCK 8
#define ROWS_PER_WARP 8
#define FULL_MASK 0xFFFFFFFFu

// Order-preserving fp32 bits -> u32 map and inverse.
__device__ __forceinline__ unsigned fmono(float f) {
    unsigned b = __float_as_uint(f);
    return b ^ ((unsigned)((int)b >> 31) | 0x80000000u);
}
__device__ __forceinline__ float funmono(unsigned u) {
    unsigned b = u ^ ((unsigned)((int)(~u) >> 31) | 0x80000000u);
    return __uint_as_float(b);
}

__global__ void __launch_bounds__(WARPS_PER_BLOCK * 32)
ctc_argmax_kernel(const float* __restrict__ em,
                  float* __restrict__ out_idx,
                  float* __restrict__ out_max,
                  int rows)
{
    const int lane = threadIdx.x & 31;
    const int warp_global = blockIdx.x * WARPS_PER_BLOCK + (threadIdx.x >> 5);
    const int base = warp_global * ROWS_PER_WARP;
    if (base >= rows) return;

    // Front-batched loads: 8 independent LDG.128, 4KB contiguous per warp.
    float4 v[ROWS_PER_WARP];
    #pragma unroll
    for (int k = 0; k < ROWS_PER_WARP; k++) {
        v[k] = reinterpret_cast<const float4*>(em + (size_t)(base + k) * V)[lane];
    }

    float res_idx[ROWS_PER_WARP];
    float res_max[ROWS_PER_WARP];

    #pragma unroll
    for (int k = 0; k < ROWS_PER_WARP; k++) {
        // Local argmax over this lane's 4 columns in mapped space.
        // Strict > keeps the earliest column on (impossible-for-normal) ties.
        unsigned m0 = fmono(v[k].x);
        unsigned m1 = fmono(v[k].y);
        unsigned m2 = fmono(v[k].z);
        unsigned m3 = fmono(v[k].w);
        unsigned best = m0; int bi = lane * 4;
        if (m1 > best) { best = m1; bi = lane * 4 + 1; }
        if (m2 > best) { best = m2; bi = lane * 4 + 2; }
        if (m3 > best) { best = m3; bi = lane * 4 + 3; }

        unsigned wmax = __reduce_max_sync(FULL_MASK, best);
        unsigned ball = __ballot_sync(FULL_MASK, best == wmax);
        int src = __ffs(ball) - 1;                  // lowest lane = lowest column
        int widx = __shfl_sync(FULL_MASK, bi, src);

        res_idx[k] = (float)widx;
        res_max[k] = funmono(wmax);
    }

    if (lane == 0) {
        // base is a multiple of 8 -> 16B-aligned float4 stores
        float4 i0 = make_float4(res_idx[0], res_idx[1], res_idx[2], res_idx[3]);
        float4 i1 = make_float4(res_idx[4], res_idx[5], res_idx[6], res_idx[7]);
        float4 m0 = make_float4(res_max[0], res_max[1], res_max[2], res_max[3]);
        float4 m1 = make_float4(res_max[4], res_max[5], res_max[6], res_max[7]);
        reinterpret_cast<float4*>(out_idx + base)[0] = i0;
        reinterpret_cast<float4*>(out_idx + base)[1] = i1;
        reinterpret_cast<float4*>(out_max + base)[0] = m0;
        reinterpret_cast<float4*>(out_max + base)[1] = m1;
    }
}

__global__ void __launch_bounds__(256)
ctc_dedup_kernel(const float* __restrict__ idx_f,   // out[0:T]
                 float* __restrict__ keep_f,        // out[T:2T]
                 float* __restrict__ score_f,       // out[2T:3T]: max in, score out
                 int rows)
{
    int i = blockIdx.x * blockDim.x + threadIdx.x;  // float4 index
    int t = i * 4;
    if (t >= rows) return;

    float4 c = reinterpret_cast<const float4*>(idx_f)[i];
    float4 s = reinterpret_cast<const float4*>(score_f)[i];
    float prev0 = (t > 0) ? idx_f[t - 1] : -1.0f;

    bool k0 = (c.x != prev0) && (c.x != (float)BLANK);
    bool k1 = (c.y != c.x)   && (c.y != (float)BLANK);
    bool k2 = (c.z != c.y)   && (c.z != (float)BLANK);
    bool k3 = (c.w != c.z)   && (c.w != (float)BLANK);

    float4 kp = make_float4(k0 ? 1.0f : 0.0f, k1 ? 1.0f : 0.0f,
                            k2 ? 1.0f : 0.0f, k3 ? 1.0f : 0.0f);
    float4 so = make_float4(k0 ? s.x : 0.0f, k1 ? s.y : 0.0f,
                            k2 ? s.z : 0.0f, k3 ? s.w : 0.0f);

    reinterpret_cast<float4*>(keep_f)[i]  = kp;
    reinterpret_cast<float4*>(score_f)[i] = so;
}

extern "C" void kernel_launch(void* const* d_in, const int* in_sizes, int n_in,
                              void* d_out, int out_size)
{
    const float* em = (const float*)d_in[0];
    float* out = (float*)d_out;

    const int rows = in_sizes[0] / V;            // T = 1048576
    float* out_idx   = out;                      // [0:T)
    float* out_keep  = out + rows;               // [T:2T)
    float* out_score = out + 2 * (size_t)rows;   // [2T:3T)

    {
        int rows_per_block = WARPS_PER_BLOCK * ROWS_PER_WARP;   // 64
        dim3 block(WARPS_PER_BLOCK * 32);
        dim3 grid((rows + rows_per_block - 1) / rows_per_block);
        ctc_argmax_kernel<<<grid, block>>>(em, out_idx, out_score, rows);
    }
    {
        int vec = (rows + 3) / 4;
        dim3 block(256);
        dim3 grid((vec + 255) / 256);
        ctc_dedup_kernel<<<grid, block>>>(out_idx, out_keep, out_score, rows);
    }
}